// round 6
// baseline (speedup 1.0000x reference)
#include <cuda_runtime.h>

#define TN 400
#define PN 4000
#define NBLOCKS 152       // one block per GB300 SM
#define TPB 800           // 25 warps x 16 targets = 400, all lanes active
#define MAXP 28           // >= ceil(PN/NBLOCKS)+1
#define ROW 72            // floats per pred row in shared

typedef unsigned long long ull;

__device__ __forceinline__ ull pk2(float lo, float hi) {
    ull r; asm("mov.b64 %0, {%1,%2};" : "=l"(r) : "f"(lo), "f"(hi)); return r;
}
__device__ __forceinline__ float2 u2f2(ull v) {
    float2 f; asm("mov.b64 {%0,%1}, %2;" : "=f"(f.x), "=f"(f.y) : "l"(v)); return f;
}
__device__ __forceinline__ ull padd2(ull a, ull b) {
    ull r; asm("add.rn.f32x2 %0, %1, %2;" : "=l"(r) : "l"(a), "l"(b)); return r;
}
__device__ __forceinline__ ull pfma2(ull a, ull b, ull c) {
    ull r; asm("fma.rn.f32x2 %0, %1, %2, %3;" : "=l"(r) : "l"(a), "l"(b), "l"(c)); return r;
}

// ptile row layout (72 floats):
//  [ 0..17] Zp kp0..8 (x,y pairs)     [18..19] 0
//  [20..35] Zp kp9..16                [36..37] 0 (half1 9th kp slot)
//  [38..39] pad
//  [40..43] {cp0, cp1, p0-p1, spp}
//  [44..52] Vp[0..8]                  [53..55] pad
//  [56..63] Vp[9..16]                 [64] 0 (half1 9th Vp)  [65..71] pad

__global__ __launch_bounds__(TPB, 1)
void matcher_kernel(const float* __restrict__ logits,   // [PN,2]
                    const float* __restrict__ pkp,      // [PN,53]
                    const int*   __restrict__ tids,     // [TN]
                    const float* __restrict__ tkp,      // [TN,53]
                    const int*   __restrict__ nbp,      // scalar num_boxes
                    float*       __restrict__ out)      // [PN,TN]
{
    __shared__ __align__(16) float ptile[MAXP * ROW];

    const int b = blockIdx.x;
    const int pbase = (b * PN) / NBLOCKS;
    const int npred = ((b + 1) * PN) / NBLOCKS - pbase;
    const int tid  = threadIdx.x;
    const int wr   = tid >> 5;
    const int lane = tid & 31;
    const int h    = lane >> 4;                // keypoint half
    const int tw   = (wr << 4) | (lane & 15);  // target 0..399

    int nbi = *nbp;
    float nb = (nbi > 0 && nbi < (1 << 20)) ? (float)nbi : *(const float*)nbp;
    const float inb = 1.0f / nb;

    // ---- pred preprocessing into shared (threads 0..npred-1, once) ----
    if (tid < npred) {
        const int gp = pbase + tid;
        const float l0 = logits[gp * 2 + 0];
        const float l1 = logits[gp * 2 + 1];
        const float m  = fmaxf(l0, l1);
        const float e0 = __expf(l0 - m);
        const float e1 = __expf(l1 - m);
        const float inv = 1.0f / (e0 + e1);
        const float p0 = e0 * inv, p1 = e1 * inv;

        const float* kp = pkp + gp * 53;
        const float c0 = kp[0], c1 = kp[1];
        float* sp = ptile + tid * ROW;
        #pragma unroll
        for (int k = 0; k < 18; ++k) sp[k] = kp[2 + k];          // kp0..8
        sp[18] = 0.0f; sp[19] = 0.0f;
        #pragma unroll
        for (int k = 0; k < 16; ++k) sp[20 + k] = kp[20 + k];    // kp9..16
        sp[36] = 0.0f; sp[37] = 0.0f; sp[38] = 0.0f; sp[39] = 0.0f;
        float sv = 0.0f;
        #pragma unroll
        for (int j = 0; j < 17; ++j) { float v = kp[36 + j]; sv = fmaf(v, v, sv); }
        sp[40] = c0;
        sp[41] = c1;
        sp[42] = p0 - p1;
        sp[43] = 0.2f * inb * sv + 0.5f * inb * (c0 * c0 + c1 * c1) - p0;  // spp
        #pragma unroll
        for (int j = 0; j < 9; ++j) sp[44 + j] = kp[36 + j];     // Vp0..8
        sp[53] = 0.0f; sp[54] = 0.0f; sp[55] = 0.0f;
        #pragma unroll
        for (int j = 0; j < 8; ++j) sp[56 + j] = kp[45 + j];     // Vp9..16
        #pragma unroll
        for (int j = 64; j < 72; ++j) sp[j] = 0.0f;
    }

    // ---- per-thread target state (9 keypoints of one half) ----
    const float* tk = tkp + tw * 53;
    const float cg0 = tk[0], cg1 = tk[1];
    const int jb  = h ? 9 : 0;
    const int cnt = h ? 8 : 9;
    ull nzg[9];
    ull w2[9];                 // {0.5*v/nb, 4.0*v/nb} — the 8x weight is baked in
    #pragma unroll
    for (int i = 0; i < 9; ++i) {
        const int j = jb + i;
        const bool ok = (i < cnt);
        nzg[i] = ok ? pk2(-tk[2 + 2 * j], -tk[3 + 2 * j]) : 0ULL;
        float v = ok ? tk[36 + j] : 0.0f;
        w2[i]  = pk2(0.5f * inb * v, 4.0f * inb * v);
    }
    const float ncgx = -cg0, ncgy = -cg1;
    float tcx = 0.0f, tcy = 0.0f, idf = 0.0f, sgt = 0.0f, cflag = 0.0f;
    if (h == 0) {
        float sv = 0.0f;
        #pragma unroll
        for (int j = 0; j < 17; ++j) { float v = tk[36 + j]; sv = fmaf(v, v, sv); }
        sgt = 0.2f * inb * sv + 0.5f * inb * (cg0 * cg0 + cg1 * cg1);
        tcx = -inb * cg0;
        tcy = -inb * cg1;
        idf = (float)tids[tw];
        cflag = 1.0f;
    }
    __syncthreads();

    const int zbase = h ? 10 : 0;       // ull index of this half's Zp
    const int vbase = 44 + h * 12;      // float index of this half's Vp
    const bool doStore = (h == 0);

    auto compute = [&](const float* pp) -> float {
        const float4 h4 = *(const float4*)(pp + 40);   // cp0, cp1, p0-p1, spp
        const ull dc2 = pk2(h4.x + ncgx, h4.y + ncgy); // (Cp-Cg) per axis

        const ull* zb = (const ull*)pp + zbase;
        ull zz[9];
        {
            const ulonglong2* z2 = (const ulonglong2*)zb;
            ulonglong2 a = z2[0], c = z2[1], d = z2[2], e = z2[3];   // LDS.128 x4
            zz[0] = a.x; zz[1] = a.y; zz[2] = c.x; zz[3] = c.y;
            zz[4] = d.x; zz[5] = d.y; zz[6] = e.x; zz[7] = e.y;
            zz[8] = zb[8];                                            // LDS.64
        }

        ull acc = 0ULL;   // lane0: offset sum (w), lane1: abs sum (8w folded)
        #pragma unroll
        for (int i = 0; i < 9; ++i) {
            ull dz = padd2(zz[i], nzg[i]);     // Zp - Zg (both axes)
            ull t  = padd2(dz, dc2);           // + (Cp - Cg)
            float2 d = u2f2(dz), u = u2f2(t);
            float a0 = fabsf(d.x) + fabsf(d.y);   // FADD with abs modifiers
            float a1 = fabsf(u.x) + fabsf(u.y);
            acc = pfma2(pk2(a0, a1), w2[i], acc);
        }
        float2 af = u2f2(acc);

        const float* vb = pp + vbase;
        const float4 v0 = *(const float4*)vb;
        const float4 v1 = *(const float4*)(vb + 4);
        const float  v8 = vb[8];
        float dv = v0.x * u2f2(w2[0]).x;
        dv = fmaf(v0.y, u2f2(w2[1]).x, dv); dv = fmaf(v0.z, u2f2(w2[2]).x, dv);
        dv = fmaf(v0.w, u2f2(w2[3]).x, dv); dv = fmaf(v1.x, u2f2(w2[4]).x, dv);
        dv = fmaf(v1.y, u2f2(w2[5]).x, dv); dv = fmaf(v1.z, u2f2(w2[6]).x, dv);
        dv = fmaf(v1.w, u2f2(w2[7]).x, dv); dv = fmaf(v8,   u2f2(w2[8]).x, dv);

        float res = af.x + af.y;              // 0.5*offset + 4*abs (weights pre-scaled)
        res = fmaf(dv, -0.8f, res);           // viz cross
        res = fmaf(h4.x, tcx, res);           // center cross x (half0 only)
        res = fmaf(h4.y, tcy, res);           // center cross y
        res = fmaf(h4.z, idf, res);           // class id*(p0-p1)
        res = fmaf(h4.w, cflag, res);         // pred constant (incl -p0)
        return res + sgt;                     // target constant
    };

    int p = 0;
    for (; p + 1 < npred; p += 2) {
        float r0 = compute(ptile + p * ROW);
        float r1 = compute(ptile + (p + 1) * ROW);
        r0 += __shfl_xor_sync(0xffffffffu, r0, 16);
        r1 += __shfl_xor_sync(0xffffffffu, r1, 16);
        if (doStore) {
            out[(size_t)(pbase + p) * TN + tw]     = r0;
            out[(size_t)(pbase + p + 1) * TN + tw] = r1;
        }
    }
    if (p < npred) {
        float r0 = compute(ptile + p * ROW);
        r0 += __shfl_xor_sync(0xffffffffu, r0, 16);
        if (doStore)
            out[(size_t)(pbase + p) * TN + tw] = r0;
    }
}

extern "C" void kernel_launch(void* const* d_in, const int* in_sizes, int n_in,
                              void* d_out, int out_size)
{
    const float* logits = (const float*)d_in[0];   // pred_logits   [8,500,2]
    const float* pkp    = (const float*)d_in[1];   // pred_keypoints[8,500,53]
    const int*   tids   = (const int*)  d_in[2];   // tgt_ids       [400]
    const float* tkp    = (const float*)d_in[3];   // tgt_keypoints [400,53]
    const int*   nbp    = (const int*)  d_in[4];   // num_boxes scalar
    (void)in_sizes; (void)n_in; (void)out_size;

    matcher_kernel<<<NBLOCKS, TPB>>>(logits, pkp, tids, tkp, nbp, (float*)d_out);
}

// round 7
// speedup vs baseline: 1.0964x; 1.0964x over previous
#include <cuda_runtime.h>

#define TN 400
#define PN 4000
#define NBLOCKS 152       // one block per GB300 SM
#define TPB 800           // 25 warps x 16 targets = 400, all lanes active
#define MAXP 28           // >= ceil(PN/NBLOCKS)+1
#define ROW 72            // floats per pred row in ptile

typedef unsigned long long ull;

__device__ __forceinline__ ull pk2(float lo, float hi) {
    ull r; asm("mov.b64 %0, {%1,%2};" : "=l"(r) : "f"(lo), "f"(hi)); return r;
}
__device__ __forceinline__ float2 u2f2(ull v) {
    float2 f; asm("mov.b64 {%0,%1}, %2;" : "=f"(f.x), "=f"(f.y) : "l"(v)); return f;
}
__device__ __forceinline__ ull padd2(ull a, ull b) {
    ull r; asm("add.rn.f32x2 %0, %1, %2;" : "=l"(r) : "l"(a), "l"(b)); return r;
}
__device__ __forceinline__ ull pfma2(ull a, ull b, ull c) {
    ull r; asm("fma.rn.f32x2 %0, %1, %2, %3;" : "=l"(r) : "l"(a), "l"(b), "l"(c)); return r;
}

// dynamic smem layout (floats):
//   stg  [0 .. 21200)                staged tkp (400 x 53)
//   sraw [21200 .. 21200+1488)       staged raw pred rows (npred x 53, padded)
//   ptile[22688 .. 22688+MAXP*ROW)   preprocessed pred rows
#define STG_OFF   0
#define SRAW_OFF  21200
#define PTILE_OFF (21200 + 1488)
#define SMEM_FLOATS (PTILE_OFF + MAXP * ROW)
#define SMEM_BYTES  (SMEM_FLOATS * 4)

__global__ __launch_bounds__(TPB, 1)
void matcher_kernel(const float* __restrict__ logits,   // [PN,2]
                    const float* __restrict__ pkp,      // [PN,53]
                    const int*   __restrict__ tids,     // [TN]
                    const float* __restrict__ tkp,      // [TN,53]
                    const int*   __restrict__ nbp,      // scalar num_boxes
                    float*       __restrict__ out)      // [PN,TN]
{
    extern __shared__ __align__(16) float dsm[];
    float* stg   = dsm + STG_OFF;
    float* sraw  = dsm + SRAW_OFF;
    float* ptile = dsm + PTILE_OFF;

    const int b = blockIdx.x;
    const int pbase = (b * PN) / NBLOCKS;
    const int npred = ((b + 1) * PN) / NBLOCKS - pbase;
    const int tid  = threadIdx.x;
    const int lane = tid & 31;
    const int h    = lane >> 4;                       // keypoint half
    const int tw   = ((tid >> 5) << 4) | (lane & 15); // target 0..399

    int nbi = *nbp;
    float nb = (nbi > 0 && nbi < (1 << 20)) ? (float)nbi : *(const float*)nbp;
    const float inb = 1.0f / nb;

    // ---- coalesced staging: targets (float4) + this block's raw preds ----
    {
        const float4* src = (const float4*)tkp;       // 21200 floats = 5300 float4
        float4* dst = (float4*)stg;
        #pragma unroll
        for (int i = 0; i < 7; ++i) {
            int idx = tid + i * TPB;
            if (idx < 5300) dst[idx] = src[idx];
        }
        const int nraw = npred * 53;
        const float* ps = pkp + pbase * 53;
        for (int i = tid; i < nraw; i += TPB) sraw[i] = ps[i];
    }
    __syncthreads();

    // ---- pred preprocessing from staged smem (threads 0..npred-1) ----
    if (tid < npred) {
        const int gp = pbase + tid;
        const float l0 = logits[gp * 2 + 0];
        const float l1 = logits[gp * 2 + 1];
        const float m  = fmaxf(l0, l1);
        const float e0 = __expf(l0 - m);
        const float e1 = __expf(l1 - m);
        const float inv = 1.0f / (e0 + e1);
        const float p0 = e0 * inv, p1 = e1 * inv;

        const float* kp = sraw + tid * 53;            // conflict-free LDS (odd stride)
        const float c0 = kp[0], c1 = kp[1];
        float* sp = ptile + tid * ROW;
        #pragma unroll
        for (int k = 0; k < 18; ++k) sp[k] = kp[2 + k];          // kp0..8
        sp[18] = 0.0f; sp[19] = 0.0f;
        #pragma unroll
        for (int k = 0; k < 16; ++k) sp[20 + k] = kp[20 + k];    // kp9..16
        sp[36] = 0.0f; sp[37] = 0.0f; sp[38] = 0.0f; sp[39] = 0.0f;
        float sv = 0.0f;
        #pragma unroll
        for (int j = 0; j < 17; ++j) { float v = kp[36 + j]; sv = fmaf(v, v, sv); }
        sp[40] = c0;
        sp[41] = c1;
        sp[42] = p0 - p1;
        sp[43] = 0.2f * inb * sv + 0.5f * inb * (c0 * c0 + c1 * c1) - p0;  // spp
        #pragma unroll
        for (int j = 0; j < 9; ++j) sp[44 + j] = kp[36 + j];     // Vp0..8
        sp[53] = 0.0f; sp[54] = 0.0f; sp[55] = 0.0f;
        #pragma unroll
        for (int j = 0; j < 8; ++j) sp[56 + j] = kp[45 + j];     // Vp9..16
        #pragma unroll
        for (int j = 64; j < 72; ++j) sp[j] = 0.0f;
    }

    // ---- per-thread target state from staged smem (conflict-free LDS) ----
    const float* tk = stg + tw * 53;
    const float cg0 = tk[0], cg1 = tk[1];
    const int jb  = h ? 9 : 0;
    const int cnt = h ? 8 : 9;
    ull nzg[9];
    ull w2[9];                 // {0.5*v/nb, 4.0*v/nb}
    #pragma unroll
    for (int i = 0; i < 9; ++i) {
        const int j = jb + i;
        const bool ok = (i < cnt);
        nzg[i] = ok ? pk2(-tk[2 + 2 * j], -tk[3 + 2 * j]) : 0ULL;
        float v = ok ? tk[36 + j] : 0.0f;
        w2[i]  = pk2(0.5f * inb * v, 4.0f * inb * v);
    }
    const float ncgx = -cg0, ncgy = -cg1;
    float tcx = 0.0f, tcy = 0.0f, idf = 0.0f, sgt = 0.0f, cflag = 0.0f;
    if (h == 0) {
        float sv = 0.0f;
        #pragma unroll
        for (int j = 0; j < 17; ++j) { float v = tk[36 + j]; sv = fmaf(v, v, sv); }
        sgt = 0.2f * inb * sv + 0.5f * inb * (cg0 * cg0 + cg1 * cg1);
        tcx = -inb * cg0;
        tcy = -inb * cg1;
        idf = (float)tids[tw];
        cflag = 1.0f;
    }
    __syncthreads();

    const int zbase = h ? 10 : 0;       // ull index of this half's Zp
    const int vbase = 44 + h * 12;      // float index of this half's Vp
    const bool doStore = (h == 0);

    auto compute = [&](const float* pp) -> float {
        const float4 h4 = *(const float4*)(pp + 40);   // cp0, cp1, p0-p1, spp
        const ull dc2 = pk2(h4.x + ncgx, h4.y + ncgy); // (Cp-Cg) per axis

        const ull* zb = (const ull*)pp + zbase;
        ull zz[9];
        {
            const ulonglong2* z2 = (const ulonglong2*)zb;
            ulonglong2 a = z2[0], c = z2[1], d = z2[2], e = z2[3];   // LDS.128 x4
            zz[0] = a.x; zz[1] = a.y; zz[2] = c.x; zz[3] = c.y;
            zz[4] = d.x; zz[5] = d.y; zz[6] = e.x; zz[7] = e.y;
            zz[8] = zb[8];                                            // LDS.64
        }

        ull acc = 0ULL;   // lane0: offset sum (0.5w), lane1: abs sum (4w)
        #pragma unroll
        for (int i = 0; i < 9; ++i) {
            ull dz = padd2(zz[i], nzg[i]);     // Zp - Zg (both axes)
            ull t  = padd2(dz, dc2);           // + (Cp - Cg)
            float2 d = u2f2(dz), u = u2f2(t);
            float a0 = fabsf(d.x) + fabsf(d.y);
            float a1 = fabsf(u.x) + fabsf(u.y);
            acc = pfma2(pk2(a0, a1), w2[i], acc);
        }
        float2 af = u2f2(acc);

        const float* vb = pp + vbase;
        const float4 v0 = *(const float4*)vb;
        const float4 v1 = *(const float4*)(vb + 4);
        const float  v8 = vb[8];
        float dv = v0.x * u2f2(w2[0]).x;
        dv = fmaf(v0.y, u2f2(w2[1]).x, dv); dv = fmaf(v0.z, u2f2(w2[2]).x, dv);
        dv = fmaf(v0.w, u2f2(w2[3]).x, dv); dv = fmaf(v1.x, u2f2(w2[4]).x, dv);
        dv = fmaf(v1.y, u2f2(w2[5]).x, dv); dv = fmaf(v1.z, u2f2(w2[6]).x, dv);
        dv = fmaf(v1.w, u2f2(w2[7]).x, dv); dv = fmaf(v8,   u2f2(w2[8]).x, dv);

        float res = af.x + af.y;
        res = fmaf(dv, -0.8f, res);           // viz cross
        res = fmaf(h4.x, tcx, res);           // center cross x (half0 only)
        res = fmaf(h4.y, tcy, res);           // center cross y
        res = fmaf(h4.z, idf, res);           // class id*(p0-p1)
        res = fmaf(h4.w, cflag, res);         // pred constant (incl -p0)
        return res + sgt;                     // target constant
    };

    int p = 0;
    for (; p + 1 < npred; p += 2) {
        float r0 = compute(ptile + p * ROW);
        float r1 = compute(ptile + (p + 1) * ROW);
        r0 += __shfl_xor_sync(0xffffffffu, r0, 16);
        r1 += __shfl_xor_sync(0xffffffffu, r1, 16);
        if (doStore) {
            out[(size_t)(pbase + p) * TN + tw]     = r0;
            out[(size_t)(pbase + p + 1) * TN + tw] = r1;
        }
    }
    if (p < npred) {
        float r0 = compute(ptile + p * ROW);
        r0 += __shfl_xor_sync(0xffffffffu, r0, 16);
        if (doStore)
            out[(size_t)(pbase + p) * TN + tw] = r0;
    }
}

extern "C" void kernel_launch(void* const* d_in, const int* in_sizes, int n_in,
                              void* d_out, int out_size)
{
    const float* logits = (const float*)d_in[0];   // pred_logits   [8,500,2]
    const float* pkp    = (const float*)d_in[1];   // pred_keypoints[8,500,53]
    const int*   tids   = (const int*)  d_in[2];   // tgt_ids       [400]
    const float* tkp    = (const float*)d_in[3];   // tgt_keypoints [400,53]
    const int*   nbp    = (const int*)  d_in[4];   // num_boxes scalar
    (void)in_sizes; (void)n_in; (void)out_size;

    static int smem_set = 0;
    if (!smem_set) {
        cudaFuncSetAttribute(matcher_kernel,
                             cudaFuncAttributeMaxDynamicSharedMemorySize, SMEM_BYTES);
        smem_set = 1;
    }
    matcher_kernel<<<NBLOCKS, TPB, SMEM_BYTES>>>(logits, pkp, tids, tkp, nbp,
                                                 (float*)d_out);
}